// round 4
// baseline (speedup 1.0000x reference)
#include <cuda_runtime.h>
#include <math.h>

// ---- problem shapes ----
#define BATCH  32
#define CIN    512
#define HW     196
#define DPROJ  8192
#define DMASK  8191

// ---- gram pipeline config ----
#define TM     128                 // c1 rows per unit tile
#define TN     64                  // c2 cols per unit tile
#define KT     49                  // K sub-tile (4*49 = 196)
#define NKT    4
#define UNITS  (BATCH * 32)        // 32 tiles/img: p in [0,4) x q in [0,8)
#define NCTA   148
#define NTHR   512                 // 256 compute + 256 scatter

// smem strides (floats)
#define ASTR   260                 // dup-packed A row: 2*TM + 4
#define BSTR   68                  // B row: TN + 4
#define SSTR   68                  // stage row: TN + 4

typedef unsigned long long ull;

// ---- device scratch ----
__device__ int   d_h[2][CIN];
__device__ float d_s[2][CIN];
__device__ float d_yacc[BATCH * DPROJ];
__device__ float d_norm[BATCH];

__device__ __forceinline__ ull ffma2(ull a, ull b, ull c) {
    ull d; asm("fma.rn.f32x2 %0, %1, %2, %3;" : "=l"(d) : "l"(a), "l"(b), "l"(c));
    return d;
}
__device__ __forceinline__ void barc() {        // compute-group-only barrier
    asm volatile("bar.sync 1, 256;" ::: "memory");
}
__device__ __forceinline__ void bars() {        // scatter-group-only barrier
    asm volatile("bar.sync 2, 256;" ::: "memory");
}

// ============================================================
// Kernel 1: extract count-sketch (h, s) from dense S1/S2.
// ============================================================
__global__ void extract_kernel(const float* __restrict__ S1,
                               const float* __restrict__ S2) {
    int wg   = (blockIdx.x << 3) + (threadIdx.x >> 5);   // 1024 warps
    int lane = threadIdx.x & 31;
    int m = wg >> 9;
    int r = wg & 511;
    const float4* S4 = (const float4*)((m ? S2 : S1) + (size_t)r * DPROJ);
    for (int i = lane; i < DPROJ / 4; i += 32) {
        float4 v = S4[i];
        int base = i << 2;
        if (v.x != 0.f) { d_h[m][r] = base + 0; d_s[m][r] = v.x; }
        if (v.y != 0.f) { d_h[m][r] = base + 1; d_s[m][r] = v.y; }
        if (v.z != 0.f) { d_h[m][r] = base + 2; d_s[m][r] = v.z; }
        if (v.w != 0.f) { d_h[m][r] = base + 3; d_s[m][r] = v.w; }
    }
}

// ============================================================
// Kernel 2: zero accumulators (graph is replayed).
// ============================================================
__global__ void zero_kernel() {
    int g = blockIdx.x * blockDim.x + threadIdx.x;
    ((float4*)d_yacc)[g] = make_float4(0.f, 0.f, 0.f, 0.f);
    if (blockIdx.x == 0 && threadIdx.x < BATCH) d_norm[threadIdx.x] = 0.f;
}

// ============================================================
// Kernel 3: warp-specialized Gram + scatter pipeline.
//   warps 0-7  (tid < 256): FFMA2 Gram tile -> stage buffer
//   warps 8-15 (tid >= 256): stage -> bins (smem atomics) -> global flush
// ============================================================
__global__ __launch_bounds__(NTHR, 1)
void gram_scatter(const float* __restrict__ x) {
    extern __shared__ float sm[];
    int*   h1s   = (int*)sm;                    // 512
    int*   h2s   = h1s + 512;                   // 512
    float* bins  = sm + 1024;                   // 8192
    float* stage = bins + DPROJ;                // TM*SSTR = 8704
    float* Ad    = stage + TM * SSTR;           // KT*ASTR = 12740
    float* Bsm   = Ad + KT * ASTR;              // KT*BSTR = 3332

    const int tid = threadIdx.x;
    const bool is_comp = (tid < 256);
    const int u0 = (int)(((long long)blockIdx.x * UNITS) / NCTA);
    const int u1 = (int)(((long long)(blockIdx.x + 1) * UNITS) / NCTA);
    const int n  = u1 - u0;

    const int ao = (tid >> 4) * 8;              // compute: 8 rows
    const int bo = (tid & 15) * 4;              // compute: 4 cols

    ull acc[8][2];
#pragma unroll
    for (int i = 0; i < 8; ++i) { acc[i][0] = 0ULL; acc[i][1] = 0ULL; }

    for (int idx = 0; idx <= n; ++idx) {
        if (is_comp) {
            if (idx < n) {
                const int u   = u0 + idx;
                const int img = u >> 5;
                const int c1  = ((u >> 3) & 3) * TM;
                const int c2  = (u & 7) * TN;
                const float* xb = x + (size_t)img * CIN * HW;

                for (int kt = 0; kt < NKT; ++kt) {
                    const int k0 = kt * KT;
                    barc();                                   // prev k-tile consumed
                    for (int l = tid; l < TM * KT; l += 256) {
                        int ci = l / KT, k = l - ci * KT;
                        float v = xb[(c1 + ci) * HW + k0 + k] * d_s[0][c1 + ci];
                        float2* dst = (float2*)&Ad[k * ASTR + 2 * ci];
                        float2 vv; vv.x = v; vv.y = v; *dst = vv;
                    }
                    for (int l = tid; l < TN * KT; l += 256) {
                        int ci = l / KT, k = l - ci * KT;
                        Bsm[k * BSTR + ci] =
                            xb[(c2 + ci) * HW + k0 + k] * d_s[1][c2 + ci];
                    }
                    barc();                                   // k-tile ready
#pragma unroll 7
                    for (int k = 0; k < KT; ++k) {
                        const float* Ar = Ad + k * ASTR + 2 * ao;
                        ulonglong2 a01 = *(const ulonglong2*)(Ar);
                        ulonglong2 a23 = *(const ulonglong2*)(Ar + 4);
                        ulonglong2 a45 = *(const ulonglong2*)(Ar + 8);
                        ulonglong2 a67 = *(const ulonglong2*)(Ar + 12);
                        ulonglong2 bb  = *(const ulonglong2*)(Bsm + k * BSTR + bo);
                        acc[0][0] = ffma2(a01.x, bb.x, acc[0][0]);
                        acc[0][1] = ffma2(a01.x, bb.y, acc[0][1]);
                        acc[1][0] = ffma2(a01.y, bb.x, acc[1][0]);
                        acc[1][1] = ffma2(a01.y, bb.y, acc[1][1]);
                        acc[2][0] = ffma2(a23.x, bb.x, acc[2][0]);
                        acc[2][1] = ffma2(a23.x, bb.y, acc[2][1]);
                        acc[3][0] = ffma2(a23.y, bb.x, acc[3][0]);
                        acc[3][1] = ffma2(a23.y, bb.y, acc[3][1]);
                        acc[4][0] = ffma2(a45.x, bb.x, acc[4][0]);
                        acc[4][1] = ffma2(a45.x, bb.y, acc[4][1]);
                        acc[5][0] = ffma2(a45.y, bb.x, acc[5][0]);
                        acc[5][1] = ffma2(a45.y, bb.y, acc[5][1]);
                        acc[6][0] = ffma2(a67.x, bb.x, acc[6][0]);
                        acc[6][1] = ffma2(a67.x, bb.y, acc[6][1]);
                        acc[7][0] = ffma2(a67.y, bb.x, acc[7][0]);
                        acc[7][1] = ffma2(a67.y, bb.y, acc[7][1]);
                    }
                }
            }
        } else {
            const int s = tid - 256;
            if (idx == 0) {
                for (int l = s; l < DPROJ; l += 256) bins[l] = 0.f;
                for (int l = s; l < CIN; l += 256) {
                    h1s[l] = d_h[0][l];
                    h2s[l] = d_h[1][l];
                }
            } else {
                const int u   = u0 + idx - 1;
                const int img = u >> 5;
                const int c1  = ((u >> 3) & 3) * TM;
                const int c2  = (u & 7) * TN;
                const int i   = s >> 1;
                const int j0  = (s & 1) * 32;
                const int h1v = h1s[c1 + i];
                const float* srow = stage + i * SSTR + j0;
#pragma unroll
                for (int e = 0; e < 8; ++e) {
                    float4 v = *(const float4*)(srow + 4 * e);
                    int jb = c2 + j0 + 4 * e;
                    atomicAdd(&bins[(h1v + h2s[jb + 0]) & DMASK], v.x);
                    atomicAdd(&bins[(h1v + h2s[jb + 1]) & DMASK], v.y);
                    atomicAdd(&bins[(h1v + h2s[jb + 2]) & DMASK], v.z);
                    atomicAdd(&bins[(h1v + h2s[jb + 3]) & DMASK], v.w);
                }
                const bool last = (idx == n);
                if (last || (((u0 + idx) >> 5) != img)) {
                    // RACE FIX: all scatter threads must finish their bin
                    // atomics for this image before anyone flushes & zeroes.
                    // Condition is uniform across the scatter group, so the
                    // named barrier is safe. bar.sync drains pending smem
                    // traffic (HW-native fence semantics).
                    bars();
                    float* yb = d_yacc + (size_t)img * DPROJ;
                    for (int l = s; l < DPROJ; l += 256) {
                        float v = bins[l];
                        if (v != 0.f) { atomicAdd(&yb[l], v); bins[l] = 0.f; }
                    }
                }
            }
        }
        __syncthreads();             // stage consumed AND acc complete
        if (is_comp && idx < n) {
#pragma unroll
            for (int i = 0; i < 8; ++i) {
                ulonglong2 w; w.x = acc[i][0]; w.y = acc[i][1];
                *(ulonglong2*)&stage[(ao + i) * SSTR + bo] = w;
                acc[i][0] = 0ULL; acc[i][1] = 0ULL;
            }
        }
        __syncthreads();             // stage refilled
    }
}

// ============================================================
// Kernel 4a: signed sqrt, write out, accumulate per-image sum-of-squares.
// grid = 32 img x 8 chunks, block 256, 4 elems/thread.
// ============================================================
__global__ void finalize1(float* __restrict__ out) {
    __shared__ float red[8];
    const int img = blockIdx.x >> 3;
    const int chunk = blockIdx.x & 7;
    const int tid = threadIdx.x;
    const float4* yb = (const float4*)(d_yacc + (size_t)img * DPROJ + chunk * 1024);
    float4* ob = (float4*)(out + (size_t)img * DPROJ + chunk * 1024);

    float4 v = yb[tid];
    float4 t;
    float* vp = (float*)&v;
    float* tp = (float*)&t;
    float ss = 0.f;
#pragma unroll
    for (int c = 0; c < 4; ++c) {
        float vv = vp[c], tt;
        if      (vv > 0.f) tt =  sqrtf( vv + 1e-8f);
        else if (vv < 0.f) tt = -sqrtf(-vv + 1e-8f);
        else               tt = 0.f;
        tp[c] = tt;
        ss += tt * tt;
    }
    ob[tid] = t;
#pragma unroll
    for (int o = 16; o; o >>= 1) ss += __shfl_xor_sync(0xFFFFFFFFu, ss, o);
    if ((tid & 31) == 0) red[tid >> 5] = ss;
    __syncthreads();
    if (tid == 0) {
        float s = 0.f;
#pragma unroll
        for (int i = 0; i < 8; ++i) s += red[i];
        atomicAdd(&d_norm[img], s);
    }
}

// ============================================================
// Kernel 4b: scale by 1/max(||y||, 1e-12).
// ============================================================
__global__ void finalize2(float* __restrict__ out) {
    const int img = blockIdx.x >> 3;
    const int chunk = blockIdx.x & 7;
    const int tid = threadIdx.x;
    float inv = 1.f / fmaxf(sqrtf(d_norm[img]), 1e-12f);
    float4* ob = (float4*)(out + (size_t)img * DPROJ + chunk * 1024);
    float4 v = ob[tid];
    v.x *= inv; v.y *= inv; v.z *= inv; v.w *= inv;
    ob[tid] = v;
}

// ============================================================
extern "C" void kernel_launch(void* const* d_in, const int* in_sizes, int n_in,
                              void* d_out, int out_size) {
    (void)in_sizes; (void)n_in; (void)out_size;
    const float* x  = (const float*)d_in[0];
    const float* S1 = (const float*)d_in[1];
    const float* S2 = (const float*)d_in[2];
    float* out = (float*)d_out;

    const int smem_bytes =
        (1024 + DPROJ + TM * SSTR + KT * ASTR + KT * BSTR) * (int)sizeof(float);
    cudaFuncSetAttribute(gram_scatter,
                         cudaFuncAttributeMaxDynamicSharedMemorySize, smem_bytes);

    extract_kernel<<<128, 256>>>(S1, S2);
    zero_kernel<<<(BATCH * DPROJ / 4) / 256, 256>>>();
    gram_scatter<<<NCTA, NTHR, smem_bytes>>>(x);
    finalize1<<<BATCH * 8, 256>>>(out);
    finalize2<<<BATCH * 8, 256>>>(out);
}